// round 3
// baseline (speedup 1.0000x reference)
#include <cuda_runtime.h>
#include <cuda_bf16.h>
#include <cstdint>

// GlobalQuantizedLatent: per-element scalar quantization vs 16-entry codebook.
// Output = 4 contiguous fp32 streams [x, quantized, z_hat, indices(float)].
//
// R3: persistent single-wave kernel. grid = 148 SMs * 6 CTAs of 256 threads
// (one wave even with reg creep) + grid-stride loop with next-iteration load
// prefetch (software pipeline). Removes ~7us of wave-transition overhead that
// the 7-wave launches in R1/R2 both paid.

__device__ __forceinline__ int quantize_one(float x, const float* __restrict__ sv,
                                            float& q_out) {
    float s = __fmaf_rn(x, 15.0f, 7.5f);      // (x + 0.5) * 15
    int k0 = __float2int_rn(s);
    k0 = min(max(k0, 0), 15);
    int km = max(k0 - 1, 0);
    int kp = min(k0 + 1, 15);

    // first-min-wins argmin over {km,k0,kp} == jnp.argmin over all 16
    float vkm = sv[km], vk0 = sv[k0], vkp = sv[kp];
    float dbest = fabsf(x - vkm);
    int   bi    = km;
    float qv    = vkm;

    float d1 = fabsf(x - vk0);
    if (d1 < dbest) { dbest = d1; bi = k0; qv = vk0; }

    float d2 = fabsf(x - vkp);
    if (d2 < dbest) { bi = kp; qv = vkp; }

    q_out = qv;
    return bi;
}

__device__ __forceinline__ void emit4(float* __restrict__ out_x,
                                      float* __restrict__ out_q,
                                      float* __restrict__ out_zh,
                                      float* __restrict__ out_idx,
                                      int i4, const float4 xv,
                                      const float* __restrict__ sv) {
    float q0, q1, q2, q3;
    int b0 = quantize_one(xv.x, sv, q0);
    int b1 = quantize_one(xv.y, sv, q1);
    int b2 = quantize_one(xv.z, sv, q2);
    int b3 = quantize_one(xv.w, sv, q3);

    float4 zh;
    zh.x = __fadd_rn(xv.x, __fsub_rn(q0, xv.x));
    zh.y = __fadd_rn(xv.y, __fsub_rn(q1, xv.y));
    zh.z = __fadd_rn(xv.z, __fsub_rn(q2, xv.z));
    zh.w = __fadd_rn(xv.w, __fsub_rn(q3, xv.w));

    float4 qv = make_float4(q0, q1, q2, q3);
    float4 iv = make_float4((float)b0, (float)b1, (float)b2, (float)b3);

    int base = i4 * 4;
    __stcs(reinterpret_cast<float4*>(out_x   + base), xv);
    __stcs(reinterpret_cast<float4*>(out_q   + base), qv);
    __stcs(reinterpret_cast<float4*>(out_zh  + base), zh);
    __stcs(reinterpret_cast<float4*>(out_idx + base), iv);
}

__global__ void __launch_bounds__(256)
gql_kernel(const float* __restrict__ x,
           const float* __restrict__ values,
           float* __restrict__ out,
           int n)
{
    __shared__ float sv[16];
    if (threadIdx.x < 16) sv[threadIdx.x] = values[threadIdx.x];
    __syncthreads();

    float* __restrict__ out_x   = out;
    float* __restrict__ out_q   = out + (size_t)n;
    float* __restrict__ out_zh  = out + 2 * (size_t)n;
    float* __restrict__ out_idx = out + 3 * (size_t)n;

    const int n4 = n >> 2;
    const int stride = gridDim.x * blockDim.x;

    int i = blockIdx.x * blockDim.x + threadIdx.x;

    // software-pipelined grid-stride loop: prefetch next chunk before
    // computing/storing the current one (keeps 2 LDG.128 in flight).
    if (i < n4) {
        float4 cur = __ldcs(reinterpret_cast<const float4*>(x) + i);
        int inext = i + stride;
        while (inext < n4) {
            float4 nxt = __ldcs(reinterpret_cast<const float4*>(x) + inext);
            emit4(out_x, out_q, out_zh, out_idx, i, cur, sv);
            cur = nxt;
            i = inext;
            inext += stride;
        }
        emit4(out_x, out_q, out_zh, out_idx, i, cur, sv);
    }

    // scalar tail (n not divisible by 4) — not hit for N=16M
    if (blockIdx.x == 0 && threadIdx.x < (n & 3)) {
        int t = (n4 << 2) + threadIdx.x;
        float xi = x[t];
        float q;
        int b = quantize_one(xi, sv, q);
        out_x[t]   = xi;
        out_q[t]   = q;
        out_zh[t]  = __fadd_rn(xi, __fsub_rn(q, xi));
        out_idx[t] = (float)b;
    }
}

extern "C" void kernel_launch(void* const* d_in, const int* in_sizes, int n_in,
                              void* d_out, int out_size) {
    const float* x      = (const float*)d_in[0];
    const float* values = (const float*)d_in[1];
    float* out = (float*)d_out;
    int n = in_sizes[0];

    const int threads = 256;
    const int sms = 148;
    const int ctas_per_sm = 6;          // one wave guaranteed (<=42 regs/thread)
    int n4 = (n + 3) / 4;
    int blocks = sms * ctas_per_sm;
    int needed = (n4 + threads - 1) / threads;
    if (blocks > needed) blocks = needed;

    gql_kernel<<<blocks, threads>>>(x, values, out, n);
}

// round 4
// speedup vs baseline: 1.1868x; 1.1868x over previous
#include <cuda_runtime.h>
#include <cuda_bf16.h>
#include <cstdint>

// GlobalQuantizedLatent: per-element scalar quantization vs 16-entry codebook.
// Output = 4 contiguous fp32 streams [x, quantized, z_hat, indices(float)].
//
// R4: revert persistent structure (R3 regressed). Flat grid like R1, but with
// sm_103a 256-bit global accesses (ld/st.global.v8.f32): 1 LDG.256 + 4 STG.256
// per thread. Halves request count per byte; each warp store covers 1024B
// contiguous with fully-covered sectors.

__device__ __forceinline__ void ld256(const float* __restrict__ p, float* v) {
    asm volatile("ld.global.v8.f32 {%0,%1,%2,%3,%4,%5,%6,%7}, [%8];"
                 : "=f"(v[0]), "=f"(v[1]), "=f"(v[2]), "=f"(v[3]),
                   "=f"(v[4]), "=f"(v[5]), "=f"(v[6]), "=f"(v[7])
                 : "l"(p));
}

__device__ __forceinline__ void st256(float* __restrict__ p, const float* v) {
    asm volatile("st.global.v8.f32 [%0], {%1,%2,%3,%4,%5,%6,%7,%8};"
                 :: "l"(p),
                    "f"(v[0]), "f"(v[1]), "f"(v[2]), "f"(v[3]),
                    "f"(v[4]), "f"(v[5]), "f"(v[6]), "f"(v[7])
                 : "memory");
}

__device__ __forceinline__ int quantize_one(float x, const float* __restrict__ sv,
                                            float& q_out) {
    float s = __fmaf_rn(x, 15.0f, 7.5f);      // (x + 0.5) * 15
    int k0 = __float2int_rn(s);
    k0 = min(max(k0, 0), 15);
    int km = max(k0 - 1, 0);
    int kp = min(k0 + 1, 15);

    // first-min-wins argmin over {km,k0,kp} == jnp.argmin over all 16
    float vkm = sv[km], vk0 = sv[k0], vkp = sv[kp];
    float dbest = fabsf(x - vkm);
    int   bi    = km;
    float qv    = vkm;

    float d1 = fabsf(x - vk0);
    if (d1 < dbest) { dbest = d1; bi = k0; qv = vk0; }

    float d2 = fabsf(x - vkp);
    if (d2 < dbest) { bi = kp; qv = vkp; }

    q_out = qv;
    return bi;
}

__global__ void __launch_bounds__(256)
gql_kernel(const float* __restrict__ x,
           const float* __restrict__ values,
           float* __restrict__ out,
           int n)
{
    __shared__ float sv[16];
    if (threadIdx.x < 16) sv[threadIdx.x] = values[threadIdx.x];
    __syncthreads();

    float* __restrict__ out_x   = out;
    float* __restrict__ out_q   = out + (size_t)n;
    float* __restrict__ out_zh  = out + 2 * (size_t)n;
    float* __restrict__ out_idx = out + 3 * (size_t)n;

    const int n8 = n >> 3;
    int i8 = blockIdx.x * blockDim.x + threadIdx.x;   // float8 index

    if (i8 < n8) {
        const int base = i8 * 8;

        float xv[8], qv[8], zh[8], iv[8];
        ld256(x + base, xv);

        #pragma unroll
        for (int j = 0; j < 8; j++) {
            int b = quantize_one(xv[j], sv, qv[j]);
            zh[j] = __fadd_rn(xv[j], __fsub_rn(qv[j], xv[j]));
            iv[j] = (float)b;
        }

        st256(out_x   + base, xv);
        st256(out_q   + base, qv);
        st256(out_zh  + base, zh);
        st256(out_idx + base, iv);
    }

    // scalar tail (n not divisible by 8) — not hit for N=16M
    if (blockIdx.x == 0 && threadIdx.x < (n & 7)) {
        int t = (n8 << 3) + threadIdx.x;
        float xi = x[t];
        float q;
        int b = quantize_one(xi, sv, q);
        out_x[t]   = xi;
        out_q[t]   = q;
        out_zh[t]  = __fadd_rn(xi, __fsub_rn(q, xi));
        out_idx[t] = (float)b;
    }
}

extern "C" void kernel_launch(void* const* d_in, const int* in_sizes, int n_in,
                              void* d_out, int out_size) {
    const float* x      = (const float*)d_in[0];
    const float* values = (const float*)d_in[1];
    float* out = (float*)d_out;
    int n = in_sizes[0];

    int n8 = (n + 7) / 8;
    int threads = 256;
    int blocks = (n8 + threads - 1) / threads;
    if (blocks < 1) blocks = 1;
    gql_kernel<<<blocks, threads>>>(x, values, out, n);
}